// round 16
// baseline (speedup 1.0000x reference)
#include <cuda_runtime.h>
#include <cuda_fp16.h>
#include <cstdint>

#define NTH    256
#define ETILE  256
#define MAX_E  800000
#define NCAP   50048

// ---- edge kernel smem layout (bytes) ----
#define SM_ROWS  0          // int[256] -> 1024
#define SM_SEG   1024       // int nseg + int seg_start[256] -> 2052, pad to 2080
#define SM_A     2080       // 256 rows x 144 B: 36864 -> 38944
#define SM_W1E   38944      // 256 rows x 144 B: 36864 -> 75808
#define SM_STAGE 75808      // 256 rows x 72 B: 18432 -> 94240
#define SMEM_EDGE 94240

// ---- pcomp kernel smem layout ----
#define PC_B1   0           // float[256]
#define PC_A    1024        // 128 rows x 272 B: 34816
#define PC_W    35840       // 256 rows x 272 B: 69632
#define SMEM_PC 105472

// ---- out kernel smem layout ----
#define FB2     0           // float[128]
#define FA      1024        // 128 rows x 528 B: 67584
#define FW      68608       // 128 rows x 528 B: 67584
#define SMEM_OUT 136192

__device__ int g_cnt[2];
__device__ int g_list[2 * MAX_E];
__device__ int g_deg[2 * NCAP];
__device__ int g_hoff[2 * NCAP];
// packed fp16 weight images in smem (ldmatrix) layout, incl. row pads
__device__ uint32_t gW1eh[2 * 256 * 36];    // [f][n<256][kpair<32 +pad]
__device__ uint32_t gW1xh[2 * 256 * 68];    // [f][n<256][kpair<64 +pad]
__device__ uint32_t gW2h [2 * 128 * 132];   // [f][n<128][kpair<128 +pad]
// P fp16, layout [f][node][q<4][j2<16] uint2; byte off = node*512 + q*128 + j2*8
__device__ uint2 g_Ph[2 * (size_t)NCAP * 64];
// per-node hidden aggregate (unpermuted cols): H[f][node][256] fp32
__device__ float g_H[2 * (size_t)NCAP * 256];

// ---------------- helpers ----------------
static __device__ __forceinline__ uint32_t smem_u32(const void* p) {
    uint32_t a;
    asm("{ .reg .u64 t; cvta.to.shared.u64 t, %1; cvt.u32.u64 %0, t; }"
        : "=r"(a) : "l"(p));
    return a;
}
static __device__ __forceinline__ uint32_t pack_h2(float lo, float hi) {
    uint32_t r;
    asm("cvt.rn.f16x2.f32 %0, %1, %2;" : "=r"(r) : "f"(hi), "f"(lo));
    return r;
}
static __device__ __forceinline__ float2 unpack_h2(uint32_t u) {
    __half2 h = *reinterpret_cast<__half2*>(&u);
    return __half22float2(h);
}
static __device__ __forceinline__ void sts128(uint32_t a, uint32_t r0, uint32_t r1,
                                              uint32_t r2, uint32_t r3) {
    asm volatile("st.shared.v4.b32 [%0], {%1,%2,%3,%4};"
                 :: "r"(a), "r"(r0), "r"(r1), "r"(r2), "r"(r3) : "memory");
}
static __device__ __forceinline__ void sts64f(uint32_t a, float r0, float r1) {
    asm volatile("st.shared.v2.f32 [%0], {%1,%2};"
                 :: "r"(a), "f"(r0), "f"(r1) : "memory");
}
static __device__ __forceinline__ void ldsm_x4(uint32_t r[4], uint32_t addr) {
    asm volatile("ldmatrix.sync.aligned.m8n8.x4.shared.b16 {%0,%1,%2,%3}, [%4];"
                 : "=r"(r[0]), "=r"(r[1]), "=r"(r[2]), "=r"(r[3]) : "r"(addr));
}
static __device__ __forceinline__ void mma_f16(float d[4], const uint32_t a[4],
                                               const uint32_t b[2]) {
    asm("mma.sync.aligned.m16n8k16.row.col.f32.f16.f16.f32 "
        "{%0,%1,%2,%3}, {%4,%5,%6,%7}, {%8,%9}, {%0,%1,%2,%3};"
        : "+f"(d[0]), "+f"(d[1]), "+f"(d[2]), "+f"(d[3])
        : "r"(a[0]), "r"(a[1]), "r"(a[2]), "r"(a[3]), "r"(b[0]), "r"(b[1]));
}
static __device__ __forceinline__ void red_add2(float* p, float a, float b) {
    asm volatile("red.global.add.v2.f32 [%0], {%1,%2};"
                 :: "l"(p), "f"(a), "f"(b) : "memory");
}
static __device__ __forceinline__ void cpa16(uint32_t d, const void* s) {
    asm volatile("cp.async.ca.shared.global [%0], [%1], 16;"
                 :: "r"(d), "l"(s) : "memory");
}
#define CP_COMMIT() asm volatile("cp.async.commit_group;" ::: "memory")
#define CP_WAIT(n)  asm volatile("cp.async.wait_group %0;" :: "n"(n) : "memory")

// ---------------- setup kernels ----------------
__global__ void prep_kernel(const float* __restrict__ W1o, const float* __restrict__ W1i,
                            const float* __restrict__ W2o, const float* __restrict__ W2i) {
    int idx = blockIdx.x * 256 + threadIdx.x;
    if (idx < 16384) {                          // W1e: [f][nl<256][p<32]
        int p = idx & 31; int t = idx >> 5;
        int nl = t & 255; int f = t >> 8;
        const float* W = f ? W1i : W1o;
        gW1eh[(f * 256 + nl) * 36 + p] =
            pack_h2(W[(128 + 2 * p) * 256 + nl], W[(129 + 2 * p) * 256 + nl]);
    } else if (idx < 49152) {                   // W1x: [f][nl<256][p<64]
        int i = idx - 16384;
        int p = i & 63; int t = i >> 6;
        int nl = t & 255; int f = t >> 8;
        const float* W = f ? W1i : W1o;
        gW1xh[(f * 256 + nl) * 68 + p] =
            pack_h2(W[(2 * p) * 256 + nl], W[(2 * p + 1) * 256 + nl]);
    } else if (idx < 81920) {                   // W2: [f][nl<128][p<128]
        int i = idx - 49152;
        int p = i & 127; int t = i >> 7;
        int nl = t & 127; int f = t >> 7;
        const float* W = f ? W2i : W2o;
        gW2h[(f * 128 + nl) * 132 + p] =
            pack_h2(W[(2 * p) * 128 + nl], W[(2 * p + 1) * 128 + nl]);
    }
}

__global__ void hist_kernel(const int* __restrict__ ei, int E) {
    int e = blockIdx.x * blockDim.x + threadIdx.x;
    if (e >= E) return;
    int r = ei[e], c = ei[E + e];
    if (r < c) atomicAdd(&g_deg[r], 1);
    else if (r > c) atomicAdd(&g_deg[NCAP + r], 1);
}

// exclusive prefix over g_deg per flavor -> g_hoff; totals -> g_cnt
__global__ void scan_kernel() {
    const int CH = 49;                          // 1024*49 >= NCAP
    int f = blockIdx.x, t = threadIdx.x;
    __shared__ int wsum[32];
    int base = t * CH;
    int sum = 0;
    for (int i = 0; i < CH; i++) {
        int idx = base + i;
        if (idx < NCAP) sum += g_deg[f * NCAP + idx];
    }
    int lane = t & 31, w = t >> 5;
    int v = sum;
    #pragma unroll
    for (int d = 1; d < 32; d <<= 1) {
        int o = __shfl_up_sync(0xffffffffu, v, d);
        if (lane >= d) v += o;
    }
    if (lane == 31) wsum[w] = v;
    __syncthreads();
    if (w == 0) {
        int x = wsum[lane];
        #pragma unroll
        for (int d = 1; d < 32; d <<= 1) {
            int o = __shfl_up_sync(0xffffffffu, x, d);
            if (lane >= d) x += o;
        }
        wsum[lane] = x;
    }
    __syncthreads();
    int excl = v - sum + (w ? wsum[w - 1] : 0);
    if (t == 1023) g_cnt[f] = excl + sum;
    int run = excl;
    for (int i = 0; i < CH; i++) {
        int idx = base + i;
        if (idx < NCAP) {
            g_hoff[f * NCAP + idx] = run;
            run += g_deg[f * NCAP + idx];
        }
    }
}

__global__ void scatter_kernel(const int* __restrict__ ei, int E) {
    int e = blockIdx.x * blockDim.x + threadIdx.x;
    if (e >= E) return;
    int r = ei[e], c = ei[E + e];
    if (r < c) {
        int pos = atomicAdd(&g_hoff[r], 1);
        g_list[pos] = e;
    } else if (r > c) {
        int pos = atomicAdd(&g_hoff[NCAP + r], 1);
        g_list[MAX_E + pos] = e;
    }
}

// ---------------- P precompute: P = x @ W1x + b1 (fp16, [node][q][j2]) -----
__global__ __launch_bounds__(256, 1)
void pcomp_kernel(const float* __restrict__ x,
                  const float* __restrict__ b1o, const float* __restrict__ b1i,
                  int N) {
    int f = blockIdx.y;
    int base = blockIdx.x * 128;
    if (base >= N) return;
    const float* b1 = f ? b1i : b1o;

    extern __shared__ __align__(16) char smem[];
    uint32_t sb = smem_u32(smem);
    uint32_t sbA = sb + PC_A, sbW = sb + PC_W;
    int tid = threadIdx.x, wid = tid >> 5, lane = tid & 31;

    {
        const uint32_t* src = gW1xh + (size_t)f * 256 * 68;
        #pragma unroll
        for (int i = 0; i < 17; i++) {
            int s = tid + i * 256;
            cpa16(sbW + s * 16, src + s * 4);
        }
        CP_COMMIT();
    }
    ((float*)(smem + PC_B1))[tid] = b1[tid];

    {
        int r = tid & 127, h = tid >> 7;
        int node = min(base + r, N - 1);
        const float4* xr = (const float4*)(x + (size_t)node * 128);
        #pragma unroll
        for (int q = 0; q < 8; q++) {
            float4 a = xr[h * 16 + 2 * q], b = xr[h * 16 + 2 * q + 1];
            sts128(sbA + r * 272 + h * 128 + q * 16,
                   pack_h2(a.x, a.y), pack_h2(a.z, a.w),
                   pack_h2(b.x, b.y), pack_h2(b.z, b.w));
        }
    }
    CP_WAIT(0);
    __syncthreads();

    uint32_t aB = sbA + (wid * 16 + (lane & 15)) * 272 + (lane >> 4) * 16;
    uint32_t bB = sbW + (uint32_t)((lane & 7) + ((lane >> 4) << 3)) * 272
                + (uint32_t)(((lane >> 3) & 1) << 4);

    float acc[32][4];
    #pragma unroll
    for (int j = 0; j < 32; j++)
        #pragma unroll
        for (int p = 0; p < 4; p++) acc[j][p] = 0.0f;

    for (int s = 0; s < 8; s++) {
        uint32_t af[4]; ldsm_x4(af, aB + s * 32);
        #pragma unroll
        for (int nt2 = 0; nt2 < 16; nt2++) {
            uint32_t bf4[4];
            ldsm_x4(bf4, bB + nt2 * 4352 + s * 32);
            mma_f16(acc[2 * nt2],     af, bf4);
            mma_f16(acc[2 * nt2 + 1], af, bf4 + 2);
        }
    }

    // epilogue: + b1, pack fp16, write [node][q][j2] as uint4 per j2-pair
    {
        const float* b1s = (const float*)(smem + PC_B1);
        int q = lane & 3, t2 = 2 * q;
        int m1 = wid * 16 + (lane >> 2), m2 = m1 + 8;
        int n1 = base + m1, n2 = base + m2;
        uint4* p1 = (uint4*)(g_Ph + ((size_t)f * NCAP + n1) * 64 + q * 16);
        uint4* p2 = (uint4*)(g_Ph + ((size_t)f * NCAP + n2) * 64 + q * 16);
        #pragma unroll
        for (int jp = 0; jp < 8; jp++) {
            uint4 v1, v2;
            #pragma unroll
            for (int s = 0; s < 2; s++) {
                int j2 = 2 * jp + s;
                int j = 2 * j2;
                float b0 = b1s[8 * j + t2],        b1v = b1s[8 * j + t2 + 1];
                float b2v = b1s[8 * (j + 1) + t2], b3 = b1s[8 * (j + 1) + t2 + 1];
                uint32_t x0 = pack_h2(acc[j][0] + b0,      acc[j][1] + b1v);
                uint32_t y0 = pack_h2(acc[j + 1][0] + b2v, acc[j + 1][1] + b3);
                uint32_t x1 = pack_h2(acc[j][2] + b0,      acc[j][3] + b1v);
                uint32_t y1 = pack_h2(acc[j + 1][2] + b2v, acc[j + 1][3] + b3);
                if (s == 0) { v1.x = x0; v1.y = y0; v2.x = x1; v2.y = y1; }
                else        { v1.z = x0; v1.w = y0; v2.z = x1; v2.w = y1; }
            }
            if (n1 < N) p1[jp] = v1;
            if (n2 < N) p2[jp] = v2;
        }
    }
}

// ---- edge kernel: sorted tiles, segment-aggregated scatter into H ---------
__global__ __launch_bounds__(NTH, 2)
void edge_kernel(const int* __restrict__ ei, const float* __restrict__ ea, int E) {
    int f = blockIdx.y;
    int cnt = g_cnt[f];
    int base = blockIdx.x * ETILE;
    if (base >= cnt) return;
    int nvalid = min(ETILE, cnt - base);
    const int* list = g_list + f * MAX_E;

    extern __shared__ __align__(16) char smem[];
    uint32_t sb = smem_u32(smem);
    int tid = threadIdx.x, wid = tid >> 5, lane = tid & 31;
    int q = lane & 3;
    int m1 = wid * 32 + (lane >> 2);

    const char* Pb = (const char*)g_Ph + (size_t)f * NCAP * 512;
    float* Hf = g_H + (size_t)f * NCAP * 256;

    // stream W1e: 2304 x 16B
    {
        const uint32_t* src = gW1eh + (size_t)f * 256 * 36;
        #pragma unroll
        for (int i = 0; i < 9; i++) {
            int s = tid + i * NTH;
            cpa16(sb + SM_W1E + s * 16, src + s * 4);
        }
        CP_COMMIT();
    }

    // headers: own edge id + row into smem (sorted -> rows ascending)
    int e_own = __ldg(list + base + min(tid, nvalid - 1));
    ((int*)(smem + SM_ROWS))[tid] = __ldg(ei + e_own);

    // P offsets for this thread's 4 fragment edges
    uint32_t poff[4];
    #pragma unroll
    for (int t = 0; t < 4; t++) {
        int m = m1 + t * 8;
        int e = __ldg(list + base + min(m, nvalid - 1));
        int node = __ldg(ei + E + e);
        poff[t] = (uint32_t)node * 512u + (uint32_t)q * 128u;
    }

    // gather own edge's ea row -> fp16 smem A
    {
        const float4* er = (const float4*)(ea + (size_t)e_own * 64);
        #pragma unroll
        for (int qq = 0; qq < 8; qq++) {
            float4 a = er[2 * qq], b = er[2 * qq + 1];
            sts128(sb + SM_A + tid * 144 + qq * 16,
                   pack_h2(a.x, a.y), pack_h2(a.z, a.w),
                   pack_h2(b.x, b.y), pack_h2(b.z, b.w));
        }
    }

    // build row segments
    int* nseg = (int*)(smem + SM_SEG);
    int* seg_start = nseg + 1;
    if (tid == 0) *nseg = 0;
    CP_WAIT(0);
    __syncthreads();
    const int* rows_s = (const int*)(smem + SM_ROWS);
    if (tid < nvalid) {
        int r = rows_s[tid];
        if (tid == 0 || rows_s[tid - 1] != r) {
            int i = atomicAdd(nseg, 1);
            seg_start[i] = tid;
        }
    }
    __syncthreads();
    int ns = *nseg;

    uint32_t bo144 = (uint32_t)((lane & 7) + ((lane >> 4) << 3)) * 144
                   + (uint32_t)(((lane >> 3) & 1) << 4);

    // A-fragments: two m16 tiles, 4 k16-steps
    uint32_t af1[2][4][4];
    #pragma unroll
    for (int t = 0; t < 2; t++) {
        uint32_t aB = sb + SM_A + (wid * 32 + t * 16 + (lane & 15)) * 144
                    + (lane >> 4) * 16;
        #pragma unroll
        for (int s = 0; s < 4; s++) ldsm_x4(af1[t][s], aB + s * 32);
    }

    uint32_t bW1 = sb + SM_W1E + bo144;
    uint32_t stq = sb + SM_STAGE + q * 8;       // + m*72 + half*32 later
    const float* stf = (const float*)(smem + SM_STAGE);

    uint2 ucur[4], unxt[4];
    for (int j2 = 0; j2 < 16; j2++) {
        if ((j2 & 1) == 0) {
            #pragma unroll
            for (int t = 0; t < 4; t++) {
                uint4 U = *(const uint4*)(Pb + poff[t] + (j2 >> 1) * 16);
                ucur[t] = make_uint2(U.x, U.y);
                unxt[t] = make_uint2(U.z, U.w);
            }
        } else {
            #pragma unroll
            for (int t = 0; t < 4; t++) ucur[t] = unxt[t];
        }
        // GEMM1 into zero acc
        float a1[2][2][4] = {};
        #pragma unroll
        for (int s = 0; s < 4; s++) {
            uint32_t bf4[4];
            ldsm_x4(bf4, bW1 + j2 * 2304 + s * 32);
            #pragma unroll
            for (int t = 0; t < 2; t++) {
                mma_f16(a1[t][0], af1[t][s], bf4);
                mma_f16(a1[t][1], af1[t][s], bf4 + 2);
            }
        }
        // +P, relu, stage to smem: stage[m][c] (c = 8*half + 2q + b), stride 72 B
        #pragma unroll
        for (int tt = 0; tt < 2; tt++) {
            #pragma unroll
            for (int ee = 0; ee < 2; ee++) {
                int e4 = 2 * tt + ee;
                int m = m1 + e4 * 8;
                float2 pl = unpack_h2(ucur[e4].x);
                float2 ph = unpack_h2(ucur[e4].y);
                uint32_t ad = stq + (uint32_t)m * 72u;
                sts64f(ad,      fmaxf(a1[tt][0][2 * ee]     + pl.x, 0.f),
                                fmaxf(a1[tt][0][2 * ee + 1] + pl.y, 0.f));
                sts64f(ad + 32, fmaxf(a1[tt][1][2 * ee]     + ph.x, 0.f),
                                fmaxf(a1[tt][1][2 * ee + 1] + ph.y, 0.f));
            }
        }
        __syncthreads();
        // segment reduce: one red.v2 per (segment, col-pair)
        for (int w = tid; w < ns * 8; w += NTH) {
            int s = w >> 3, c2 = (w & 7) * 2;
            int m0 = seg_start[s];
            int r = rows_s[m0];
            float s0 = 0.f, s1 = 0.f;
            int m = m0;
            do {
                s0 += stf[m * 18 + c2];
                s1 += stf[m * 18 + c2 + 1];
                m++;
            } while (m < nvalid && rows_s[m] == r);
            red_add2(Hf + (size_t)r * 256 + 16 * j2 + c2, s0, s1);
        }
        __syncthreads();
    }
}

// ---------------- out kernel: out = H_fp16 @ W2 + deg*b2 -------------------
__global__ __launch_bounds__(256, 1)
void out_kernel(const float* __restrict__ b2o, const float* __restrict__ b2i,
                int N, float* __restrict__ out) {
    int f = blockIdx.y;
    int base = blockIdx.x * 128;
    if (base >= N) return;
    int colOff = f ? 0 : 128;
    const float* b2 = f ? b2i : b2o;

    extern __shared__ __align__(16) char smem[];
    uint32_t sb = smem_u32(smem);
    int tid = threadIdx.x, wid = tid >> 5, lane = tid & 31;

    {
        const uint32_t* src = gW2h + (size_t)f * 128 * 132;
        #pragma unroll
        for (int i = 0; i < 17; i++) {
            int s = tid + i * 256;
            if (s < 4224) cpa16(sb + FW + s * 16, src + s * 4);
        }
        CP_COMMIT();
    }
    if (tid < 128) ((float*)(smem + FB2))[tid] = b2[tid];

    // load H rows -> fp16 smem A, stride 528 B
    {
        int r = tid & 127, h = tid >> 7;
        int node = min(base + r, N - 1);
        const float4* Hr = (const float4*)(g_H + ((size_t)f * NCAP + node) * 256
                                           + h * 128);
        #pragma unroll
        for (int i = 0; i < 16; i++) {
            float4 a = Hr[2 * i], b = Hr[2 * i + 1];
            sts128(sb + FA + r * 528 + h * 256 + i * 16,
                   pack_h2(a.x, a.y), pack_h2(a.z, a.w),
                   pack_h2(b.x, b.y), pack_h2(b.z, b.w));
        }
    }
    CP_WAIT(0);
    __syncthreads();

    uint32_t aB = sb + FA + (wid * 16 + (lane & 15)) * 528 + (lane >> 4) * 16;
    uint32_t bB = sb + FW + (uint32_t)((lane & 7) + ((lane >> 4) << 3)) * 528
                + (uint32_t)(((lane >> 3) & 1) << 4);

    float acc[16][4];
    #pragma unroll
    for (int j = 0; j < 16; j++)
        #pragma unroll
        for (int p = 0; p < 4; p++) acc[j][p] = 0.0f;

    for (int s = 0; s < 16; s++) {
        uint32_t af[4]; ldsm_x4(af, aB + s * 32);
        #pragma unroll
        for (int nt2 = 0; nt2 < 8; nt2++) {
            uint32_t bf4[4];
            ldsm_x4(bf4, bB + nt2 * 8448 + s * 32);
            mma_f16(acc[2 * nt2],     af, bf4);
            mma_f16(acc[2 * nt2 + 1], af, bf4 + 2);
        }
    }

    // epilogue: + deg*b2, dense writes
    {
        const float* b2s = (const float*)(smem + FB2);
        int q = lane & 3, t2 = 2 * q;
        int m1 = wid * 16 + (lane >> 2), m2 = m1 + 8;
        int n1 = base + m1, n2 = base + m2;
        if (n1 < N) {
            float d = (float)g_deg[f * NCAP + n1];
            float* o = out + (size_t)n1 * 256 + colOff;
            #pragma unroll
            for (int nt = 0; nt < 16; nt++) {
                int n0 = 8 * nt + t2;
                *(float2*)(o + n0) = make_float2(acc[nt][0] + d * b2s[n0],
                                                 acc[nt][1] + d * b2s[n0 + 1]);
            }
        }
        if (n2 < N) {
            float d = (float)g_deg[f * NCAP + n2];
            float* o = out + (size_t)n2 * 256 + colOff;
            #pragma unroll
            for (int nt = 0; nt < 16; nt++) {
                int n0 = 8 * nt + t2;
                *(float2*)(o + n0) = make_float2(acc[nt][2] + d * b2s[n0],
                                                 acc[nt][3] + d * b2s[n0 + 1]);
            }
        }
    }
}

// ---------------- host launch ----------------
extern "C" void kernel_launch(void* const* d_in, const int* in_sizes, int n_in,
                              void* d_out, int out_size) {
    const float* x   = (const float*)d_in[0];
    const int*   ei  = (const int*)  d_in[1];
    const float* ea  = (const float*)d_in[2];
    const float* W1o = (const float*)d_in[3];
    const float* b1o = (const float*)d_in[4];
    const float* W2o = (const float*)d_in[5];
    const float* b2o = (const float*)d_in[6];
    const float* W1i = (const float*)d_in[7];
    const float* b1i = (const float*)d_in[8];
    const float* W2i = (const float*)d_in[9];
    const float* b2i = (const float*)d_in[10];
    float* out = (float*)d_out;
    int E = in_sizes[1] / 2;
    int N = in_sizes[0] / 128;
    if (N > NCAP) N = NCAP;

    static float* dH = nullptr;
    static int* dDeg = nullptr;
    static bool attr_set = false;
    if (!attr_set) {
        cudaFuncSetAttribute(edge_kernel, cudaFuncAttributeMaxDynamicSharedMemorySize,
                             SMEM_EDGE);
        cudaFuncSetAttribute(pcomp_kernel, cudaFuncAttributeMaxDynamicSharedMemorySize,
                             SMEM_PC);
        cudaFuncSetAttribute(out_kernel, cudaFuncAttributeMaxDynamicSharedMemorySize,
                             SMEM_OUT);
        cudaGetSymbolAddress((void**)&dH, g_H);
        cudaGetSymbolAddress((void**)&dDeg, g_deg);
        attr_set = true;
    }

    cudaMemsetAsync(dH, 0, 2 * (size_t)NCAP * 256 * sizeof(float));
    cudaMemsetAsync(dDeg, 0, 2 * NCAP * sizeof(int));
    prep_kernel<<<320, 256>>>(W1o, W1i, W2o, W2i);
    hist_kernel<<<(E + 511) / 512, 512>>>(ei, E);
    scan_kernel<<<2, 1024>>>();
    scatter_kernel<<<(E + 511) / 512, 512>>>(ei, E);
    pcomp_kernel<<<dim3((N + 127) / 128, 2), 256, SMEM_PC>>>(x, b1o, b1i, N);

    dim3 egrid((E + ETILE - 1) / ETILE, 2);
    edge_kernel<<<egrid, NTH, SMEM_EDGE>>>(ei, ea, E);

    dim3 ogrid((N + 127) / 128, 2);
    out_kernel<<<ogrid, 256, SMEM_OUT>>>(b2o, b2i, N, out);
}

// round 17
// speedup vs baseline: 2.1033x; 2.1033x over previous
#include <cuda_runtime.h>
#include <cuda_fp16.h>
#include <cstdint>

#define TILE   128
#define NTH    128
#define MAX_E  800000
#define NCAP   50048

// ---- mlp kernel smem layout (bytes) ----
#define SM_ROWS 0          // int[128]
#define SM_EIDX 512        // int[128]
#define SM_B2   1024       // float[128]
#define SM_A    1536       // 128 rows x 144 B: 18432 -> ends 19968
#define SM_W1E  19968      // 256 rows x 144 B: 36864 -> ends 56832
#define SM_W2C  56832      // 2 chunks x (128 rows x 144 B) = 36864 -> ends 93696
#define SMEM_MLP 93696

// ---- pcomp kernel smem layout ----
#define PC_B1   0          // float[256]
#define PC_A    1024       // 128 rows x 272 B: 34816
#define PC_W    35840      // 256 rows x 272 B: 69632
#define SMEM_PC 105472

__device__ int g_cnt[2];
__device__ int g_list[2 * MAX_E];
// packed fp16 weight images in smem (ldmatrix) layout, incl. row pads
__device__ uint32_t gW1eh[2 * 256 * 36];    // [f][n<256][kpair<32 +pad]
__device__ uint32_t gW1xh[2 * 256 * 68];    // [f][n<256][kpair<64 +pad]
__device__ uint32_t gW2h [2 * 128 * 132];   // [f][n<128][kpair<128 +pad]
// P fp16, layout [f][node][q<4][j2<16] uint2; byte off = node*512 + q*128 + j2*8
__device__ uint2 g_Ph[2 * (size_t)NCAP * 64];

// ---------------- helpers ----------------
static __device__ __forceinline__ uint32_t smem_u32(const void* p) {
    uint32_t a;
    asm("{ .reg .u64 t; cvta.to.shared.u64 t, %1; cvt.u32.u64 %0, t; }"
        : "=r"(a) : "l"(p));
    return a;
}
static __device__ __forceinline__ uint32_t pack_h2(float lo, float hi) {
    uint32_t r;
    asm("cvt.rn.f16x2.f32 %0, %1, %2;" : "=r"(r) : "f"(hi), "f"(lo));
    return r;
}
static __device__ __forceinline__ float2 unpack_h2(uint32_t u) {
    __half2 h = *reinterpret_cast<__half2*>(&u);
    return __half22float2(h);
}
static __device__ __forceinline__ void sts128(uint32_t a, uint32_t r0, uint32_t r1,
                                              uint32_t r2, uint32_t r3) {
    asm volatile("st.shared.v4.b32 [%0], {%1,%2,%3,%4};"
                 :: "r"(a), "r"(r0), "r"(r1), "r"(r2), "r"(r3) : "memory");
}
static __device__ __forceinline__ void ldsm_x4(uint32_t r[4], uint32_t addr) {
    asm volatile("ldmatrix.sync.aligned.m8n8.x4.shared.b16 {%0,%1,%2,%3}, [%4];"
                 : "=r"(r[0]), "=r"(r[1]), "=r"(r[2]), "=r"(r[3]) : "r"(addr));
}
static __device__ __forceinline__ void mma_f16(float d[4], const uint32_t a[4],
                                               const uint32_t b[2]) {
    asm("mma.sync.aligned.m16n8k16.row.col.f32.f16.f16.f32 "
        "{%0,%1,%2,%3}, {%4,%5,%6,%7}, {%8,%9}, {%0,%1,%2,%3};"
        : "+f"(d[0]), "+f"(d[1]), "+f"(d[2]), "+f"(d[3])
        : "r"(a[0]), "r"(a[1]), "r"(a[2]), "r"(a[3]), "r"(b[0]), "r"(b[1]));
}
static __device__ __forceinline__ void red_add2(float* p, float a, float b) {
    asm volatile("red.global.add.v2.f32 [%0], {%1,%2};"
                 :: "l"(p), "f"(a), "f"(b) : "memory");
}
static __device__ __forceinline__ void cpa16(uint32_t d, const void* s) {
    asm volatile("cp.async.ca.shared.global [%0], [%1], 16;"
                 :: "r"(d), "l"(s) : "memory");
}
#define CP_COMMIT() asm volatile("cp.async.commit_group;" ::: "memory")
#define CP_WAIT(n)  asm volatile("cp.async.wait_group %0;" :: "n"(n) : "memory")

// ---------------- setup kernels ----------------
__global__ void prep_kernel(const float* __restrict__ W1o, const float* __restrict__ W1i,
                            const float* __restrict__ W2o, const float* __restrict__ W2i) {
    int idx = blockIdx.x * 256 + threadIdx.x;
    if (idx < 2) g_cnt[idx] = 0;
    if (idx < 16384) {                          // W1e: [f][nl<256][p<32]
        int p = idx & 31; int t = idx >> 5;
        int nl = t & 255; int f = t >> 8;
        const float* W = f ? W1i : W1o;
        gW1eh[(f * 256 + nl) * 36 + p] =
            pack_h2(W[(128 + 2 * p) * 256 + nl], W[(129 + 2 * p) * 256 + nl]);
    } else if (idx < 49152) {                   // W1x: [f][nl<256][p<64]
        int i = idx - 16384;
        int p = i & 63; int t = i >> 6;
        int nl = t & 255; int f = t >> 8;
        const float* W = f ? W1i : W1o;
        gW1xh[(f * 256 + nl) * 68 + p] =
            pack_h2(W[(2 * p) * 256 + nl], W[(2 * p + 1) * 256 + nl]);
    } else if (idx < 81920) {                   // W2: [f][nl<128][p<128]
        int i = idx - 49152;
        int p = i & 127; int t = i >> 7;
        int nl = t & 127; int f = t >> 7;
        const float* W = f ? W2i : W2o;
        gW2h[(f * 128 + nl) * 132 + p] =
            pack_h2(W[(2 * p) * 128 + nl], W[(2 * p + 1) * 128 + nl]);
    }
}

__global__ void partition_kernel(const int* __restrict__ ei, int E) {
    __shared__ int s_cnt[2], s_base[2];
    int tid = threadIdx.x;
    if (tid < 2) s_cnt[tid] = 0;
    __syncthreads();
    int e = blockIdx.x * blockDim.x + tid;
    bool valid = e < E;
    int r = 0, c = 0;
    if (valid) { r = ei[e]; c = ei[E + e]; }
    int lane = tid & 31;
    bool po = valid && (r < c);
    bool pi = valid && (r > c);
    unsigned mo = __ballot_sync(0xffffffffu, po);
    unsigned mi = __ballot_sync(0xffffffffu, pi);
    int lo = __ffs(mo) - 1, li = __ffs(mi) - 1;
    int wo = 0, wi = 0;
    if (mo && lane == lo) wo = atomicAdd(&s_cnt[0], __popc(mo));
    if (mi && lane == li) wi = atomicAdd(&s_cnt[1], __popc(mi));
    __syncthreads();
    if (tid == 0) s_base[0] = atomicAdd(&g_cnt[0], s_cnt[0]);
    if (tid == 1) s_base[1] = atomicAdd(&g_cnt[1], s_cnt[1]);
    __syncthreads();
    if (mo) wo = __shfl_sync(0xffffffffu, wo, lo);
    if (mi) wi = __shfl_sync(0xffffffffu, wi, li);
    unsigned lt = (1u << lane) - 1u;
    if (po) g_list[s_base[0] + wo + __popc(mo & lt)] = e;
    if (pi) g_list[MAX_E + s_base[1] + wi + __popc(mi & lt)] = e;
}

// ---------------- P precompute: P = x @ W1x + b1 (fp16, [node][q][j2]) -----
__global__ __launch_bounds__(256, 1)
void pcomp_kernel(const float* __restrict__ x,
                  const float* __restrict__ b1o, const float* __restrict__ b1i,
                  int N) {
    int f = blockIdx.y;
    int base = blockIdx.x * 128;
    if (base >= N) return;
    const float* b1 = f ? b1i : b1o;

    extern __shared__ __align__(16) char smem[];
    uint32_t sb = smem_u32(smem);
    uint32_t sbA = sb + PC_A, sbW = sb + PC_W;
    int tid = threadIdx.x, wid = tid >> 5, lane = tid & 31;

    {
        const uint32_t* src = gW1xh + (size_t)f * 256 * 68;
        #pragma unroll
        for (int i = 0; i < 17; i++) {
            int s = tid + i * 256;
            cpa16(sbW + s * 16, src + s * 4);
        }
        CP_COMMIT();
    }
    ((float*)(smem + PC_B1))[tid] = b1[tid];

    {
        int r = tid & 127, h = tid >> 7;
        int node = min(base + r, N - 1);
        const float4* xr = (const float4*)(x + (size_t)node * 128);
        #pragma unroll
        for (int q = 0; q < 8; q++) {
            float4 a = xr[h * 16 + 2 * q], b = xr[h * 16 + 2 * q + 1];
            sts128(sbA + r * 272 + h * 128 + q * 16,
                   pack_h2(a.x, a.y), pack_h2(a.z, a.w),
                   pack_h2(b.x, b.y), pack_h2(b.z, b.w));
        }
    }
    CP_WAIT(0);
    __syncthreads();

    uint32_t aB = sbA + (wid * 16 + (lane & 15)) * 272 + (lane >> 4) * 16;
    uint32_t bB = sbW + (uint32_t)((lane & 7) + ((lane >> 4) << 3)) * 272
                + (uint32_t)(((lane >> 3) & 1) << 4);

    float acc[32][4];
    #pragma unroll
    for (int j = 0; j < 32; j++)
        #pragma unroll
        for (int p = 0; p < 4; p++) acc[j][p] = 0.0f;

    for (int s = 0; s < 8; s++) {
        uint32_t af[4]; ldsm_x4(af, aB + s * 32);
        #pragma unroll
        for (int nt2 = 0; nt2 < 16; nt2++) {
            uint32_t bf4[4];
            ldsm_x4(bf4, bB + nt2 * 4352 + s * 32);
            mma_f16(acc[2 * nt2],     af, bf4);
            mma_f16(acc[2 * nt2 + 1], af, bf4 + 2);
        }
    }

    // epilogue: + b1, pack fp16, write [node][q][j2] as uint4 per j2-pair
    {
        const float* b1s = (const float*)(smem + PC_B1);
        int q = lane & 3, t2 = 2 * q;
        int m1 = wid * 16 + (lane >> 2), m2 = m1 + 8;
        int n1 = base + m1, n2 = base + m2;
        uint4* p1 = (uint4*)(g_Ph + ((size_t)f * NCAP + n1) * 64 + q * 16);
        uint4* p2 = (uint4*)(g_Ph + ((size_t)f * NCAP + n2) * 64 + q * 16);
        #pragma unroll
        for (int jp = 0; jp < 8; jp++) {
            uint4 v1, v2;
            #pragma unroll
            for (int s = 0; s < 2; s++) {
                int j2 = 2 * jp + s;
                int j = 2 * j2;
                float b0 = b1s[8 * j + t2],        b1v = b1s[8 * j + t2 + 1];
                float b2v = b1s[8 * (j + 1) + t2], b3 = b1s[8 * (j + 1) + t2 + 1];
                uint32_t x0 = pack_h2(acc[j][0] + b0,      acc[j][1] + b1v);
                uint32_t y0 = pack_h2(acc[j + 1][0] + b2v, acc[j + 1][1] + b3);
                uint32_t x1 = pack_h2(acc[j][2] + b0,      acc[j][3] + b1v);
                uint32_t y1 = pack_h2(acc[j + 1][2] + b2v, acc[j + 1][3] + b3);
                if (s == 0) { v1.x = x0; v1.y = y0; v2.x = x1; v2.y = y1; }
                else        { v1.z = x0; v1.w = y0; v2.z = x1; v2.w = y1; }
            }
            if (n1 < N) p1[jp] = v1;
            if (n2 < N) p2[jp] = v2;
        }
    }
}

// ---------------- W2 quarter-chunk copy (32 kpairs = 128 B per n-row) -------
static __device__ __forceinline__ void cp_w2_chunk(int f, int c, uint32_t dst, int tid) {
    const uint32_t* src = gW2h + (size_t)f * 128 * 132 + c * 32;
    #pragma unroll
    for (int i = 0; i < 8; i++) {
        int s = tid + i * NTH;          // s < 1024
        int nl = s >> 3, seg = s & 7;
        cpa16(dst + nl * 144 + seg * 16, src + (size_t)nl * 132 + seg * 4);
    }
}

// ---------------- main edge-MLP kernel (4 warps, m=32/warp, 2 CTAs/SM) -----
__global__ __launch_bounds__(NTH, 2)
void mlp_kernel(const int* __restrict__ ei, const float* __restrict__ ea,
                const float* __restrict__ b2o, const float* __restrict__ b2i,
                int E, float* __restrict__ out) {
    int f = blockIdx.y;
    int cnt = g_cnt[f];
    int base = blockIdx.x * TILE;
    if (base >= cnt) return;
    int nvalid = min(TILE, cnt - base);
    const int* list = g_list + f * MAX_E;
    int colOff = f ? 0 : 128;
    const float* b2 = f ? b2i : b2o;

    extern __shared__ __align__(16) char smem[];
    uint32_t sb = smem_u32(smem);
    uint32_t sbA = sb + SM_A;
    int tid = threadIdx.x, wid = tid >> 5, lane = tid & 31;
    int q = lane & 3;
    int m1 = wid * 32 + (lane >> 2);
    int m2 = m1 + 8, m3 = m1 + 16, m4 = m1 + 24;

    // P byte-offsets: node*512 + q*128 (layout [node][q][j2], j2 stride 8 B)
    const char* Pb = (const char*)g_Ph + (size_t)f * NCAP * 512;
    uint32_t poff[4];
    {
        int mm[4] = { m1, m2, m3, m4 };
        #pragma unroll
        for (int t = 0; t < 4; t++) {
            int e = __ldg(list + base + min(mm[t], nvalid - 1));
            int node = __ldg(ei + E + e);
            poff[t] = (uint32_t)node * 512u + (uint32_t)q * 128u;
        }
    }

    // stream W1e (group 1): 2304 x 16B;  W2 chunks 0,1 (groups 2,3)
    {
        const uint32_t* src = gW1eh + (size_t)f * 256 * 36;
        #pragma unroll
        for (int i = 0; i < 18; i++) {
            int s = tid + i * NTH;
            cpa16(sb + SM_W1E + s * 16, src + s * 4);
        }
        CP_COMMIT();
    }
    cp_w2_chunk(f, 0, sb + SM_W2C, tid);          CP_COMMIT();
    cp_w2_chunk(f, 1, sb + SM_W2C + 18432, tid);  CP_COMMIT();

    // headers
    {
        int e = list[base + min(tid, nvalid - 1)];
        ((int*)(smem + SM_EIDX))[tid] = e;
        ((int*)(smem + SM_ROWS))[tid] = ei[e];
        ((float*)(smem + SM_B2))[tid] = b2[tid];
    }
    __syncthreads();

    // ---- gather A = edge_attr as f16, one full row per thread ----
    {
        int eidx = ((const int*)(smem + SM_EIDX))[tid];
        const float4* er = (const float4*)(ea + (size_t)eidx * 64);
        #pragma unroll
        for (int qq = 0; qq < 8; qq++) {
            float4 a = er[2 * qq], b = er[2 * qq + 1];
            sts128(sbA + tid * 144 + qq * 16,
                   pack_h2(a.x, a.y), pack_h2(a.z, a.w),
                   pack_h2(b.x, b.y), pack_h2(b.z, b.w));
        }
    }
    CP_WAIT(2);          // W1e resident
    __syncthreads();

    uint32_t bo144 = (uint32_t)((lane & 7) + ((lane >> 4) << 3)) * 144
                   + (uint32_t)(((lane >> 3) & 1) << 4);

    // A-fragments for both m16 tiles, all 4 k16-steps (held in regs)
    uint32_t af1[2][4][4];
    #pragma unroll
    for (int t = 0; t < 2; t++) {
        uint32_t aB = sbA + (wid * 32 + t * 16 + (lane & 15)) * 144 + (lane >> 4) * 16;
        #pragma unroll
        for (int s = 0; s < 4; s++) ldsm_x4(af1[t][s], aB + s * 32);
    }

    float acc2[2][16][4];
    #pragma unroll
    for (int t = 0; t < 2; t++)
        #pragma unroll
        for (int j = 0; j < 16; j++)
            #pragma unroll
            for (int p = 0; p < 4; p++) acc2[t][j][p] = 0.0f;

    uint32_t bW1 = sb + SM_W1E + bo144;

    // ---- fused loop: h n-tile pair j2 (GEMM1 into zero acc, +P after) ------
    uint2 ucur[4], unxt[4];
    #pragma unroll
    for (int c = 0; c < 4; c++) {
        if (c < 3) CP_WAIT(1); else CP_WAIT(0);
        __syncthreads();
        uint32_t bW2 = sb + SM_W2C + (c & 1) * 18432 + bo144;
        #pragma unroll
        for (int ks = 0; ks < 4; ks++) {
            int j2 = c * 4 + ks;
            if ((ks & 1) == 0) {
                #pragma unroll
                for (int t = 0; t < 4; t++) {
                    uint4 U = *(const uint4*)(Pb + poff[t] + (j2 >> 1) * 16);
                    ucur[t] = make_uint2(U.x, U.y);
                    unxt[t] = make_uint2(U.z, U.w);
                }
            } else {
                #pragma unroll
                for (int t = 0; t < 4; t++) ucur[t] = unxt[t];
            }
            // GEMM1 into zero-initialized a1
            float a1[2][2][4] = {};
            #pragma unroll
            for (int s = 0; s < 4; s++) {
                uint32_t bf4[4];
                ldsm_x4(bf4, bW1 + j2 * 2304 + s * 32);
                #pragma unroll
                for (int t = 0; t < 2; t++) {
                    mma_f16(a1[t][0], af1[t][s], bf4);
                    mma_f16(a1[t][1], af1[t][s], bf4 + 2);
                }
            }
            // + P, relu, pack -> GEMM2 A-fragments
            uint32_t af[2][4];
            {
                float2 l0 = unpack_h2(ucur[0].x), h0 = unpack_h2(ucur[0].y);
                float2 l1 = unpack_h2(ucur[1].x), h1 = unpack_h2(ucur[1].y);
                af[0][0] = pack_h2(fmaxf(a1[0][0][0] + l0.x, 0.f),
                                   fmaxf(a1[0][0][1] + l0.y, 0.f));
                af[0][1] = pack_h2(fmaxf(a1[0][0][2] + l1.x, 0.f),
                                   fmaxf(a1[0][0][3] + l1.y, 0.f));
                af[0][2] = pack_h2(fmaxf(a1[0][1][0] + h0.x, 0.f),
                                   fmaxf(a1[0][1][1] + h0.y, 0.f));
                af[0][3] = pack_h2(fmaxf(a1[0][1][2] + h1.x, 0.f),
                                   fmaxf(a1[0][1][3] + h1.y, 0.f));
                float2 l2 = unpack_h2(ucur[2].x), h2v = unpack_h2(ucur[2].y);
                float2 l3 = unpack_h2(ucur[3].x), h3 = unpack_h2(ucur[3].y);
                af[1][0] = pack_h2(fmaxf(a1[1][0][0] + l2.x, 0.f),
                                   fmaxf(a1[1][0][1] + l2.y, 0.f));
                af[1][1] = pack_h2(fmaxf(a1[1][0][2] + l3.x, 0.f),
                                   fmaxf(a1[1][0][3] + l3.y, 0.f));
                af[1][2] = pack_h2(fmaxf(a1[1][1][0] + h2v.x, 0.f),
                                   fmaxf(a1[1][1][1] + h2v.y, 0.f));
                af[1][3] = pack_h2(fmaxf(a1[1][1][2] + h3.x, 0.f),
                                   fmaxf(a1[1][1][3] + h3.y, 0.f));
            }
            // GEMM2: B fragment shared across both m-tiles
            #pragma unroll
            for (int nt2 = 0; nt2 < 8; nt2++) {
                uint32_t bf4[4];
                ldsm_x4(bf4, bW2 + nt2 * 2304 + ks * 32);
                #pragma unroll
                for (int t = 0; t < 2; t++) {
                    mma_f16(acc2[t][2 * nt2],     af[t], bf4);
                    mma_f16(acc2[t][2 * nt2 + 1], af[t], bf4 + 2);
                }
            }
        }
        __syncthreads();
        if (c < 2) { cp_w2_chunk(f, c + 2, sb + SM_W2C + (c & 1) * 18432, tid); CP_COMMIT(); }
    }

    // ---- epilogue: + b2, vectorized scatter-add (4 m-rows per thread) ----
    {
        const float* b2s = (const float*)(smem + SM_B2);
        const int* rows = (const int*)(smem + SM_ROWS);
        int mm[4] = { m1, m2, m3, m4 };
        int t2 = 2 * q;
        #pragma unroll
        for (int t = 0; t < 4; t++) {
            bool ok = mm[t] < nvalid;
            if (!ok) continue;
            float* o = out + (size_t)rows[mm[t]] * 256 + colOff;
            int ti = t >> 1, hi = (t & 1) ? 2 : 0;
            #pragma unroll
            for (int nt = 0; nt < 16; nt++) {
                int n0 = 8 * nt + t2;
                red_add2(o + n0, acc2[ti][nt][hi] + b2s[n0],
                                 acc2[ti][nt][hi + 1] + b2s[n0 + 1]);
            }
        }
    }
}

// ---------------- host launch ----------------
extern "C" void kernel_launch(void* const* d_in, const int* in_sizes, int n_in,
                              void* d_out, int out_size) {
    const float* x   = (const float*)d_in[0];
    const int*   ei  = (const int*)  d_in[1];
    const float* ea  = (const float*)d_in[2];
    const float* W1o = (const float*)d_in[3];
    const float* b1o = (const float*)d_in[4];
    const float* W2o = (const float*)d_in[5];
    const float* b2o = (const float*)d_in[6];
    const float* W1i = (const float*)d_in[7];
    const float* b1i = (const float*)d_in[8];
    const float* W2i = (const float*)d_in[9];
    const float* b2i = (const float*)d_in[10];
    float* out = (float*)d_out;
    int E = in_sizes[1] / 2;
    int N = in_sizes[0] / 128;
    if (N > NCAP) N = NCAP;

    static bool attr_set = false;
    if (!attr_set) {
        cudaFuncSetAttribute(mlp_kernel, cudaFuncAttributeMaxDynamicSharedMemorySize,
                             SMEM_MLP);
        cudaFuncSetAttribute(pcomp_kernel, cudaFuncAttributeMaxDynamicSharedMemorySize,
                             SMEM_PC);
        attr_set = true;
    }

    cudaMemsetAsync(d_out, 0, (size_t)out_size * sizeof(float));
    prep_kernel<<<320, 256>>>(W1o, W1i, W2o, W2i);   // also resets g_cnt
    partition_kernel<<<(E + 511) / 512, 512>>>(ei, E);
    pcomp_kernel<<<dim3((N + 127) / 128, 2), 256, SMEM_PC>>>(x, b1o, b1i, N);

    dim3 grid((E + TILE - 1) / TILE, 2);
    mlp_kernel<<<grid, NTH, SMEM_MLP>>>(ei, ea, b2o, b2i, E, out);
}